// round 4
// baseline (speedup 1.0000x reference)
#include <cuda_runtime.h>

#define B_ROWS 8192
#define P_ROWS 1024
#define D_DIM  256
#define NPART  64          // prototype partial-reduction blocks
#define GRID   512         // 4 blocks/SM * 128 SMs worth; all-resident at <=64 regs
#define ROWS_PER_BLK (B_ROWS / GRID)   // 16
#define TILE_BYTES   (ROWS_PER_BLK * D_DIM * 4)  // 16384

// Scratch + barrier state (device globals: allocation-free rule)
__device__ float g_partial[NPART * D_DIM];   // per-block column sums of prototypes
__device__ float g_p2[NPART];                // per-block sum of squares
__device__ float g_m2[D_DIM];                // 2 * mean_p proto[:,d]
__device__ float g_c;                        // mean_p ||p||^2
__device__ unsigned int g_count = 0;         // phase-1 arrivals
__device__ unsigned int g_flag  = 0;         // combine-done flag
__device__ unsigned int g_done  = 0;         // exit counter (reset)

__device__ __forceinline__ void cp_async16(void* smem_dst, const void* gmem_src) {
    unsigned int s;
    asm("{ .reg .u64 t; cvta.to.shared.u64 t, %1; cvt.u32.u64 %0, t; }"
        : "=r"(s) : "l"(smem_dst));
    asm volatile("cp.async.cg.shared.global [%0], [%1], 16;" :: "r"(s), "l"(gmem_src));
}

__global__ void __launch_bounds__(256, 4)
som_fused(const float* __restrict__ x,
          const float* __restrict__ proto,
          float* __restrict__ out) {
    const int tid  = threadIdx.x;
    const int lane = tid & 31;
    const int warp = tid >> 5;
    const int blk  = blockIdx.x;

    __shared__ __align__(16) float sm_x[ROWS_PER_BLK * D_DIM];  // 16 KB x tile
    __shared__ __align__(16) float sm_grp[4 * D_DIM];           // proto row-group partials
    __shared__ float sm_p2g[8];

    // ---- Step 0: issue async copy of this block's 16 x-rows IMMEDIATELY ------
    // Overlaps with the entire prototype reduction + barriers.
    {
        const char* src = reinterpret_cast<const char*>(x) + (size_t)blk * TILE_BYTES;
#pragma unroll
        for (int r = 0; r < 4; ++r) {
            int chunk = tid + r * 256;               // 1024 chunks of 16B
            cp_async16(reinterpret_cast<char*>(sm_x) + chunk * 16,
                       src + chunk * 16);
        }
        asm volatile("cp.async.commit_group;");
    }

    // ---- Phase 1: prototype partials (blocks 0..63, 16 rows each) ------------
    if (blk < NPART) {
        const int c4   = tid & 63;                   // column group (4 floats)
        const int g    = tid >> 6;                   // 4 row-groups of 4 rows
        const int row0 = blk * (P_ROWS / NPART) + g * 4;

        float4 s = make_float4(0.f, 0.f, 0.f, 0.f);
        float sq = 0.f;
#pragma unroll
        for (int r = 0; r < 4; ++r) {
            float4 v = *reinterpret_cast<const float4*>(
                proto + (row0 + r) * D_DIM + c4 * 4);
            s.x += v.x; s.y += v.y; s.z += v.z; s.w += v.w;
            sq  += v.x * v.x + v.y * v.y + v.z * v.z + v.w * v.w;
        }
        *reinterpret_cast<float4*>(&sm_grp[g * D_DIM + c4 * 4]) = s;

#pragma unroll
        for (int o = 16; o > 0; o >>= 1)
            sq += __shfl_down_sync(0xFFFFFFFFu, sq, o);
        if (lane == 0) sm_p2g[warp] = sq;
        __syncthreads();

        float col = sm_grp[tid] + sm_grp[D_DIM + tid] +
                    sm_grp[2 * D_DIM + tid] + sm_grp[3 * D_DIM + tid];
        g_partial[blk * D_DIM + tid] = col;
        if (tid == 0) {
            float p2 = 0.f;
#pragma unroll
            for (int i = 0; i < 8; ++i) p2 += sm_p2g[i];
            g_p2[blk] = p2;
        }
        __syncthreads();
        if (tid == 0) {
            __threadfence();
            atomicAdd(&g_count, 1u);
        }
    }

    // ---- Combine: block 0 only (kills the redundant 39MB L2 storm) -----------
    if (blk == 0) {
        if (tid == 0) {
            while (atomicAdd(&g_count, 0u) < NPART) { }
        }
        __syncthreads();
        __threadfence();

        float s = 0.f;
#pragma unroll 8
        for (int i = 0; i < NPART; ++i)
            s += __ldcg(&g_partial[i * D_DIM + tid]);   // column tid
        g_m2[tid] = s * (2.0f / (float)P_ROWS);

        if (warp == 0) {
            float v = __ldcg(&g_p2[lane]) + __ldcg(&g_p2[lane + 32]);
#pragma unroll
            for (int o = 16; o > 0; o >>= 1)
                v += __shfl_down_sync(0xFFFFFFFFu, v, o);
            if (lane == 0) g_c = v * (1.0f / (float)P_ROWS);
        }
        __syncthreads();
        if (tid == 0) {
            __threadfence();
            atomicExch(&g_flag, 1u);
        }
    }

    // ---- All blocks: wait for combined stats (single flag, implies phase 1) --
    if (tid == 0) {
        while (atomicAdd(&g_flag, 0u) == 0u) { }
    }
    __syncthreads();
    __threadfence();

    // Broadcast read of m2/c (1KB per block, L2-resident)
    const int d0 = lane * 8;
    float4 m0, m1;
    m0.x = __ldcg(&g_m2[d0 + 0]); m0.y = __ldcg(&g_m2[d0 + 1]);
    m0.z = __ldcg(&g_m2[d0 + 2]); m0.w = __ldcg(&g_m2[d0 + 3]);
    m1.x = __ldcg(&g_m2[d0 + 4]); m1.y = __ldcg(&g_m2[d0 + 5]);
    m1.z = __ldcg(&g_m2[d0 + 6]); m1.w = __ldcg(&g_m2[d0 + 7]);
    const float c = __ldcg(&g_c);

    // ---- Phase 3: consume the prefetched x tile (2 rows per warp) ------------
    asm volatile("cp.async.wait_group 0;");
    __syncthreads();

    const int r0 = warp * 2;           // local rows r0, r0+1
    const float4* xr0 = reinterpret_cast<const float4*>(&sm_x[r0 * D_DIM + d0]);
    const float4* xr1 = reinterpret_cast<const float4*>(&sm_x[(r0 + 1) * D_DIM + d0]);

    float4 a0 = xr0[0], a1 = xr0[1];
    float4 b0 = xr1[0], b1 = xr1[1];

    float acc0, acc1;
    acc0  = a0.x * (a0.x - m0.x);  acc1  = b0.x * (b0.x - m0.x);
    acc0 += a0.y * (a0.y - m0.y);  acc1 += b0.y * (b0.y - m0.y);
    acc0 += a0.z * (a0.z - m0.z);  acc1 += b0.z * (b0.z - m0.z);
    acc0 += a0.w * (a0.w - m0.w);  acc1 += b0.w * (b0.w - m0.w);
    acc0 += a1.x * (a1.x - m1.x);  acc1 += b1.x * (b1.x - m1.x);
    acc0 += a1.y * (a1.y - m1.y);  acc1 += b1.y * (b1.y - m1.y);
    acc0 += a1.z * (a1.z - m1.z);  acc1 += b1.z * (b1.z - m1.z);
    acc0 += a1.w * (a1.w - m1.w);  acc1 += b1.w * (b1.w - m1.w);

#pragma unroll
    for (int o = 16; o > 0; o >>= 1) {
        acc0 += __shfl_down_sync(0xFFFFFFFFu, acc0, o);
        acc1 += __shfl_down_sync(0xFFFFFFFFu, acc1, o);
    }

    const int rowg = blk * ROWS_PER_BLK + r0;
    if (lane == 0) {
        out[rowg]     = acc0 + c;
        out[rowg + 1] = acc1 + c;
    }

    // ---- Reset barrier state for the next graph replay -----------------------
    __syncthreads();
    if (tid == 0) {
        unsigned int d = atomicAdd(&g_done, 1u);
        if (d == GRID - 1) {
            g_count = 0;
            g_flag  = 0;
            g_done  = 0;
            __threadfence();
        }
    }
}

extern "C" void kernel_launch(void* const* d_in, const int* in_sizes, int n_in,
                              void* d_out, int out_size) {
    const float* x     = (const float*)d_in[0];  // (8192, 256) float32
    const float* proto = (const float*)d_in[1];  // (1024, 256) float32
    float* out = (float*)d_out;                  // (8192,) float32

    som_fused<<<GRID, 256>>>(x, proto, out);
}

// round 7
// speedup vs baseline: 2.8426x; 2.8426x over previous
#include <cuda_runtime.h>

#define B_ROWS 8192
#define P_ROWS 1024
#define D_DIM  256
#define NPART  16          // prototype partial-reduction blocks (64 rows each)
#define GRID   512         // <= 148 SMs * 4 resident blocks at <=64 regs: barrier-safe
#define ROWS_PER_BLK (B_ROWS / GRID)             // 16
#define TILE_BYTES   (ROWS_PER_BLK * D_DIM * 4)  // 16384

// Scratch + barrier state (device globals: allocation-free rule)
__device__ float g_partial[NPART * D_DIM];   // per-block column sums of prototypes
__device__ float g_p2[NPART];                // per-block sum of squares
__device__ unsigned int g_count = 0;         // phase-1 arrivals
__device__ unsigned int g_done  = 0;         // exit counter (reset)

__device__ __forceinline__ void cp_async16(void* smem_dst, const void* gmem_src) {
    unsigned int s;
    asm("{ .reg .u64 t; cvta.to.shared.u64 t, %1; cvt.u32.u64 %0, t; }"
        : "=r"(s) : "l"(smem_dst));
    asm volatile("cp.async.cg.shared.global [%0], [%1], 16;" :: "r"(s), "l"(gmem_src));
}

// Acquire load for the spin: orders subsequent loads after the observation,
// and the "memory" clobber stops the compiler moving data loads across it.
__device__ __forceinline__ unsigned int ld_acq_u32(const unsigned int* p) {
    unsigned int v;
    asm volatile("ld.acquire.gpu.global.u32 %0, [%1];" : "=r"(v) : "l"(p) : "memory");
    return v;
}

__global__ void __launch_bounds__(256, 4)
som_fused(const float* __restrict__ x,
          const float* __restrict__ proto,
          float* __restrict__ out) {
    const int tid  = threadIdx.x;
    const int lane = tid & 31;
    const int warp = tid >> 5;
    const int blk  = blockIdx.x;

    __shared__ __align__(16) float sm_x[ROWS_PER_BLK * D_DIM];  // 16 KB x tile
    __shared__ __align__(16) float sm_grp[4 * D_DIM];           // row-group partials
    __shared__ float sm_p2g[8];
    __shared__ float sm_c;

    // ---- Step 0: issue async copy of this block's 16 x-rows IMMEDIATELY ------
    // Overlaps the prototype reduction and the barrier spin.
    {
        const char* src = reinterpret_cast<const char*>(x) + (size_t)blk * TILE_BYTES;
#pragma unroll
        for (int r = 0; r < 4; ++r) {
            int chunk = tid + r * 256;               // 1024 chunks of 16B
            cp_async16(reinterpret_cast<char*>(sm_x) + chunk * 16,
                       src + chunk * 16);
        }
        asm volatile("cp.async.commit_group;");
    }

    // ---- Phase 1: prototype partials (blocks 0..15, 64 rows each) ------------
    if (blk < NPART) {
        const int c4   = tid & 63;                   // column group (4 floats)
        const int g    = tid >> 6;                   // 4 row-groups of 16 rows
        const int row0 = blk * (P_ROWS / NPART) + g * 16;

        float4 s = make_float4(0.f, 0.f, 0.f, 0.f);
        float sq = 0.f;
#pragma unroll
        for (int r = 0; r < 16; ++r) {               // MLP=16 float4 loads
            float4 v = *reinterpret_cast<const float4*>(
                proto + (row0 + r) * D_DIM + c4 * 4);
            s.x += v.x; s.y += v.y; s.z += v.z; s.w += v.w;
            sq  += v.x * v.x + v.y * v.y + v.z * v.z + v.w * v.w;
        }
        *reinterpret_cast<float4*>(&sm_grp[g * D_DIM + c4 * 4]) = s;

#pragma unroll
        for (int o = 16; o > 0; o >>= 1)
            sq += __shfl_down_sync(0xFFFFFFFFu, sq, o);
        if (lane == 0) sm_p2g[warp] = sq;
        __syncthreads();

        float col = sm_grp[tid] + sm_grp[D_DIM + tid] +
                    sm_grp[2 * D_DIM + tid] + sm_grp[3 * D_DIM + tid];
        g_partial[blk * D_DIM + tid] = col;
        if (tid == 0) {
            float p2 = 0.f;
#pragma unroll
            for (int i = 0; i < 8; ++i) p2 += sm_p2g[i];
            g_p2[blk] = p2;
        }

        // RACE FIX (R6): EVERY thread fences its own global store before the
        // block's arrival is published. tid0-only fencing left 255 threads'
        // g_partial stores unordered w.r.t. the atomicAdd.
        __threadfence();
        __syncthreads();
        if (tid == 0) {
            atomicAdd(&g_count, 1u);     // arrival (all writes fenced above)
        }
    }

    // ---- Grid barrier: acquire-load spin (no atomic-ALU contention) ----------
    if (tid == 0) {
        while (ld_acq_u32(&g_count) < NPART) { }
    }
    __syncthreads();

    // ---- Combine: every block, redundant, 16 KB L2-resident ------------------
    {
        float s = 0.f;
#pragma unroll
        for (int i = 0; i < NPART; ++i)
            s += __ldcg(&g_partial[i * D_DIM + tid]);   // column tid, coalesced

        __shared__ __align__(16) float sm_m2tmp[D_DIM];
        sm_m2tmp[tid] = s * (2.0f / (float)P_ROWS);

        // p2 reduce: ALL 32 lanes of warp 0 participate (R5 deadlock fix).
        if (warp == 0) {
            float v = (lane < NPART) ? __ldcg(&g_p2[lane]) : 0.0f;
#pragma unroll
            for (int o = 16; o > 0; o >>= 1)
                v += __shfl_down_sync(0xFFFFFFFFu, v, o);
            if (lane == 0) sm_c = v * (1.0f / (float)P_ROWS);
        }
        __syncthreads();

        // ---- Phase 3: consume the prefetched x tile (2 rows per warp) --------
        const float c  = sm_c;
        const int  d0  = lane * 8;
        const float4 m0 = *reinterpret_cast<const float4*>(&sm_m2tmp[d0]);
        const float4 m1 = *reinterpret_cast<const float4*>(&sm_m2tmp[d0 + 4]);

        asm volatile("cp.async.wait_group 0;");
        __syncthreads();

        const int r0 = warp * 2;
        const float4* xr0 = reinterpret_cast<const float4*>(&sm_x[r0 * D_DIM + d0]);
        const float4* xr1 = reinterpret_cast<const float4*>(&sm_x[(r0 + 1) * D_DIM + d0]);

        float4 a0 = xr0[0], a1 = xr0[1];
        float4 b0 = xr1[0], b1 = xr1[1];

        float acc0, acc1;
        acc0  = a0.x * (a0.x - m0.x);  acc1  = b0.x * (b0.x - m0.x);
        acc0 += a0.y * (a0.y - m0.y);  acc1 += b0.y * (b0.y - m0.y);
        acc0 += a0.z * (a0.z - m0.z);  acc1 += b0.z * (b0.z - m0.z);
        acc0 += a0.w * (a0.w - m0.w);  acc1 += b0.w * (b0.w - m0.w);
        acc0 += a1.x * (a1.x - m1.x);  acc1 += b1.x * (b1.x - m1.x);
        acc0 += a1.y * (a1.y - m1.y);  acc1 += b1.y * (b1.y - m1.y);
        acc0 += a1.z * (a1.z - m1.z);  acc1 += b1.z * (b1.z - m1.z);
        acc0 += a1.w * (a1.w - m1.w);  acc1 += b1.w * (b1.w - m1.w);

#pragma unroll
        for (int o = 16; o > 0; o >>= 1) {
            acc0 += __shfl_down_sync(0xFFFFFFFFu, acc0, o);
            acc1 += __shfl_down_sync(0xFFFFFFFFu, acc1, o);
        }

        const int rowg = blk * ROWS_PER_BLK + r0;
        if (lane == 0) {
            out[rowg]     = acc0 + c;
            out[rowg + 1] = acc1 + c;
        }
    }

    // ---- Reset barrier state for the next graph replay -----------------------
    __syncthreads();
    if (tid == 0) {
        unsigned int d = atomicAdd(&g_done, 1u);
        if (d == GRID - 1) {             // last block out resets everything
            g_count = 0;
            g_done  = 0;
            __threadfence();
        }
    }
}

extern "C" void kernel_launch(void* const* d_in, const int* in_sizes, int n_in,
                              void* d_out, int out_size) {
    const float* x     = (const float*)d_in[0];  // (8192, 256) float32
    const float* proto = (const float*)d_in[1];  // (1024, 256) float32
    float* out = (float*)d_out;                  // (8192,) float32

    som_fused<<<GRID, 256>>>(x, proto, out);
}